// round 1
// baseline (speedup 1.0000x reference)
#include <cuda_runtime.h>
#include <math.h>

// Problem constants
#define NB 8
#define NL 384
#define ND 1024
#define NE 4
#define NH 4096
#define MTOT (NB * NL)   // 3072 tokens

// Scratch: gating weights + one hidden-activation buffer (reused across slots,
// safe because all launches are sequential on one stream / in the graph).
__device__ float g_w_be[NB * NE];
__device__ float g_h[(size_t)MTOT * NH];   // 50.3 MB fp32 scratch

__device__ __forceinline__ float gelu_tanh(float x) {
    // jax.nn.gelu(approximate=True)
    float x3 = x * x * x;
    return 0.5f * x * (1.0f + tanhf(0.7978845608028654f * (x + 0.044715f * x3)));
}

// ---------------------------------------------------------------------------
// Gating kernel: one block per batch. Computes segment aggregates, gate
// logits, time-modulation, softmax, top-2, normalized weights -> g_w_be.
// ---------------------------------------------------------------------------
__global__ void gate_kernel(const float* __restrict__ x,
                            const float* __restrict__ tc,
                            const float* __restrict__ gW,   // (4, 3072)
                            const float* __restrict__ gb,   // (4,)
                            const float* __restrict__ tmW,  // (8, 1024)
                            const float* __restrict__ tmb)  // (8,)
{
    int b = blockIdx.x;
    int t = threadIdx.x;  // 256 threads

    float logit[4] = {0.f, 0.f, 0.f, 0.f};
    float modv[8]  = {0.f, 0.f, 0.f, 0.f, 0.f, 0.f, 0.f, 0.f};

    const float* xb = x + (size_t)b * NL * ND;

    for (int d = t; d < ND; d += 256) {
        float hs = 0.f, ws = 0.f, ps = 0.f;
        for (int l = 0;   l < 128; l++) hs += xb[(size_t)l * ND + d];
        for (int l = 128; l < 256; l++) ws += xb[(size_t)l * ND + d];
        for (int l = 256; l < 384; l++) ps += xb[(size_t)l * ND + d];
        float full = (hs + ws + ps) * (1.0f / 384.0f);
        float hp   = (hs + ps) * (1.0f / 256.0f);
        float wp   = (ws + ps) * (1.0f / 256.0f);
        #pragma unroll
        for (int e = 0; e < 4; e++) {
            const float* w = gW + (size_t)e * 3 * ND;
            logit[e] += full * w[d] + hp * w[ND + d] + wp * w[2 * ND + d];
        }
        float v = tc[(size_t)b * ND + d];
        float s = v / (1.0f + expf(-v));   // silu
        #pragma unroll
        for (int j = 0; j < 8; j++) modv[j] += s * tmW[(size_t)j * ND + d];
    }

    __shared__ float red[12][256];
    #pragma unroll
    for (int v = 0; v < 4; v++) red[v][t] = logit[v];
    #pragma unroll
    for (int v = 0; v < 8; v++) red[4 + v][t] = modv[v];
    __syncthreads();
    for (int s = 128; s > 0; s >>= 1) {
        if (t < s) {
            #pragma unroll
            for (int v = 0; v < 12; v++) red[v][t] += red[v][t + s];
        }
        __syncthreads();
    }

    if (t == 0) {
        float lg[4];
        #pragma unroll
        for (int e = 0; e < 4; e++) {
            float sc = red[4 + e][0] + tmb[e];      // scale
            float sh = red[8 + e][0] + tmb[4 + e];  // shift
            lg[e] = (red[e][0] + gb[e]) * (1.0f + sc) + sh;
        }
        float mx = fmaxf(fmaxf(lg[0], lg[1]), fmaxf(lg[2], lg[3]));
        float ex[4], sum = 0.f;
        #pragma unroll
        for (int e = 0; e < 4; e++) { ex[e] = expf(lg[e] - mx); sum += ex[e]; }
        float sc4[4];
        #pragma unroll
        for (int e = 0; e < 4; e++) sc4[e] = ex[e] / sum;

        // top-2 (earliest index wins ties, matching jax top_k)
        int i1 = 0;
        for (int e = 1; e < 4; e++) if (sc4[e] > sc4[i1]) i1 = e;
        int i2 = -1;
        for (int e = 0; e < 4; e++) {
            if (e == i1) continue;
            if (i2 < 0 || sc4[e] > sc4[i2]) i2 = e;
        }
        float denom = sc4[i1] + sc4[i2] + 1e-8f;
        #pragma unroll
        for (int e = 0; e < 4; e++) g_w_be[b * 4 + e] = 0.0f;
        g_w_be[b * 4 + i1] = sc4[i1] / denom;
        g_w_be[b * 4 + i2] = sc4[i2] / denom;
    }
}

// ---------------------------------------------------------------------------
// SGEMM: C[M=3072 x N] = A[M x K] @ B[K x N] (+ epilogue)
//   mode 0: C = gelu(acc + bias)            (GEMM1, writes g_h)
//   mode 1: C = acc + bias                  (shared GEMM2, writes out)
//   mode 2: C += w_be * (acc + bias)        (expert GEMM2, accumulates)
// e >= 0 enables per-batch expert skipping + mask-segment skipping.
// 128x128 block tile, K-tile 16, 8x8 per thread, 256 threads.
// ---------------------------------------------------------------------------
__global__ __launch_bounds__(256, 2)
void sgemm_kernel(const float* __restrict__ A, const float* __restrict__ Bm,
                  const float* __restrict__ bias, float* __restrict__ C,
                  int K, int N, int e, int mode)
{
    int mt = blockIdx.y;            // m-tile: 128 tokens; b = mt/3, seg = mt%3
    float wgt = 1.0f;
    if (e >= 0) {
        int b = mt / 3, seg = mt % 3;
        if ((e == 1 && seg == 1) || (e == 2 && seg == 0)) return;  // mask==0
        wgt = g_w_be[b * NE + e];
        if (wgt == 0.0f) return;                                    // not selected
    }

    __shared__ float As[16][132];
    __shared__ float Bs[16][132];

    int tid = threadIdx.x;
    int tn = tid & 15;
    int tm = tid >> 4;

    const float* Ab = A + (size_t)(mt * 128) * K;
    const float* Bb = Bm + blockIdx.x * 128;

    float acc[8][8];
    #pragma unroll
    for (int i = 0; i < 8; i++)
        #pragma unroll
        for (int j = 0; j < 8; j++) acc[i][j] = 0.0f;

    for (int kt = 0; kt < K; kt += 16) {
        // Load A tile (128 x 16), store transposed As[k][m]
        #pragma unroll
        for (int i = 0; i < 2; i++) {
            int idx = tid * 2 + i;          // 0..511
            int r = idx >> 2, c4 = idx & 3;
            const float4 v = *(const float4*)(Ab + (size_t)r * K + kt + c4 * 4);
            As[c4 * 4 + 0][r] = v.x;
            As[c4 * 4 + 1][r] = v.y;
            As[c4 * 4 + 2][r] = v.z;
            As[c4 * 4 + 3][r] = v.w;
        }
        // Load B tile (16 x 128)
        #pragma unroll
        for (int i = 0; i < 2; i++) {
            int idx = tid * 2 + i;
            int r = idx >> 5, c4 = idx & 31;
            *(float4*)(&Bs[r][c4 * 4]) =
                *(const float4*)(Bb + (size_t)(kt + r) * N + c4 * 4);
        }
        __syncthreads();

        #pragma unroll
        for (int k = 0; k < 16; k++) {
            float a[8], bb[8];
            #pragma unroll
            for (int j = 0; j < 8; j++) a[j] = As[k][tm * 8 + j];
            #pragma unroll
            for (int j = 0; j < 8; j++) bb[j] = Bs[k][tn * 8 + j];
            #pragma unroll
            for (int i = 0; i < 8; i++)
                #pragma unroll
                for (int j = 0; j < 8; j++)
                    acc[i][j] = fmaf(a[i], bb[j], acc[i][j]);
        }
        __syncthreads();
    }

    int rbase = mt * 128 + tm * 8;
    int cbase = blockIdx.x * 128 + tn * 8;

    if (mode == 0) {
        #pragma unroll
        for (int i = 0; i < 8; i++) {
            float* Crow = C + (size_t)(rbase + i) * N + cbase;
            #pragma unroll
            for (int j = 0; j < 8; j++)
                Crow[j] = gelu_tanh(acc[i][j] + bias[cbase + j]);
        }
    } else if (mode == 1) {
        #pragma unroll
        for (int i = 0; i < 8; i++) {
            float* Crow = C + (size_t)(rbase + i) * N + cbase;
            #pragma unroll
            for (int j = 0; j < 8; j++)
                Crow[j] = acc[i][j] + bias[cbase + j];
        }
    } else {
        #pragma unroll
        for (int i = 0; i < 8; i++) {
            float* Crow = C + (size_t)(rbase + i) * N + cbase;
            #pragma unroll
            for (int j = 0; j < 8; j++)
                Crow[j] += wgt * (acc[i][j] + bias[cbase + j]);
        }
    }
}

// ---------------------------------------------------------------------------
// kernel_launch: gating, shared MLP, then 4 expert slots (self-skipping).
// All launches on the default stream -> deterministic, graph-capturable.
// ---------------------------------------------------------------------------
extern "C" void kernel_launch(void* const* d_in, const int* in_sizes, int n_in,
                              void* d_out, int out_size)
{
    const float* x    = (const float*)d_in[0];   // (8,384,1024)
    const float* tc   = (const float*)d_in[1];   // (8,1024)
    const float* gW   = (const float*)d_in[2];   // (4,3072)
    const float* gb   = (const float*)d_in[3];   // (4,)
    const float* tmW  = (const float*)d_in[4];   // (8,1024)
    const float* tmb  = (const float*)d_in[5];   // (8,)
    const float* eW1  = (const float*)d_in[6];   // (4,1024,4096)
    const float* eb1  = (const float*)d_in[7];   // (4,4096)
    const float* eW2  = (const float*)d_in[8];   // (4,4096,1024)
    const float* eb2  = (const float*)d_in[9];   // (4,1024)
    const float* sW1  = (const float*)d_in[10];  // (1024,4096)
    const float* sb1  = (const float*)d_in[11];  // (4096,)
    const float* sW2  = (const float*)d_in[12];  // (4096,1024)
    const float* sb2  = (const float*)d_in[13];  // (1024,)
    float* out = (float*)d_out;                  // (8,384,1024)

    float* hbuf = nullptr;
    cudaGetSymbolAddress((void**)&hbuf, g_h);

    gate_kernel<<<NB, 256>>>(x, tc, gW, gb, tmW, tmb);

    dim3 g1(NH / 128, MTOT / 128);  // (32, 24) for GEMM1 (N=4096)
    dim3 g2(ND / 128, MTOT / 128);  // (8, 24)  for GEMM2 (N=1024)

    // Shared path: writes 'out' fully (out is poisoned before timing).
    sgemm_kernel<<<g1, 256>>>(x,    sW1, sb1, hbuf, ND, NH, -1, 0);
    sgemm_kernel<<<g2, 256>>>(hbuf, sW2, sb2, out,  NH, ND, -1, 1);

    // Expert paths: blocks self-skip via g_w_be and the segment mask.
    for (int e = 0; e < NE; e++) {
        sgemm_kernel<<<g1, 256>>>(x, eW1 + (size_t)e * ND * NH,
                                  eb1 + (size_t)e * NH, hbuf, ND, NH, e, 0);
        sgemm_kernel<<<g2, 256>>>(hbuf, eW2 + (size_t)e * NH * ND,
                                  eb2 + (size_t)e * ND, out, NH, ND, e, 2);
    }
}

// round 3
// speedup vs baseline: 3.8953x; 3.8953x over previous
#include <cuda_runtime.h>
#include <cuda_bf16.h>
#include <cstdint>
#include <math.h>

// Problem constants
#define NB 8
#define NL 384
#define ND 1024
#define NE 4
#define NH 4096
#define MTOT (NB * NL)   // 3072 tokens

// ---------------------------------------------------------------------------
// Device scratch (static __device__ arrays; no runtime allocation)
// ---------------------------------------------------------------------------
__device__ float g_w_be[NB * NE];

__device__ __align__(16) __nv_bfloat16 g_x_hi[(size_t)MTOT * ND];
__device__ __align__(16) __nv_bfloat16 g_x_lo[(size_t)MTOT * ND];
__device__ __align__(16) __nv_bfloat16 g_h_hi[(size_t)MTOT * NH];
__device__ __align__(16) __nv_bfloat16 g_h_lo[(size_t)MTOT * NH];

// Transposed weights arena: all B operands stored [N][K] K-major bf16 hi/lo.
#define WT_TOTAL (40u * 1024u * 1024u)
__device__ __align__(16) __nv_bfloat16 g_wt_hi[WT_TOTAL];
__device__ __align__(16) __nv_bfloat16 g_wt_lo[WT_TOTAL];

#define OFF_SW1T  ((size_t)0)
#define OFF_SW2T  ((size_t)4 * 1024 * 1024)
#define OFF_EW1T(e) ((size_t)8  * 1024 * 1024 + (size_t)(e) * 4 * 1024 * 1024)
#define OFF_EW2T(e) ((size_t)24 * 1024 * 1024 + (size_t)(e) * 4 * 1024 * 1024)

// ---------------------------------------------------------------------------
// Target-independent PTX helpers (sm_80+; compiles for plain sm_103)
// ---------------------------------------------------------------------------
__device__ __forceinline__ uint32_t smem_to_u32(const void* p) {
    uint32_t a;
    asm("{ .reg .u64 t; cvta.to.shared.u64 t, %1; cvt.u32.u64 %0, t; }"
        : "=r"(a) : "l"(p));
    return a;
}

__device__ __forceinline__ void cp_async16(uint32_t dst, const void* src) {
    asm volatile("cp.async.cg.shared.global [%0], [%1], 16;"
                 :: "r"(dst), "l"(src));
}
#define CP_COMMIT() asm volatile("cp.async.commit_group;" ::: "memory")
#define CP_WAIT(n)  asm volatile("cp.async.wait_group %0;" :: "n"(n) : "memory")

#define LDSM_X4(r, addr) \
    asm volatile("ldmatrix.sync.aligned.m8n8.x4.shared.b16 {%0,%1,%2,%3}, [%4];" \
        : "=r"((r)[0]), "=r"((r)[1]), "=r"((r)[2]), "=r"((r)[3]) \
        : "r"(addr))

#define MMA_BF16(d, a, b) \
    asm volatile("mma.sync.aligned.m16n8k16.row.col.f32.bf16.bf16.f32 " \
        "{%0,%1,%2,%3}, {%4,%5,%6,%7}, {%8,%9}, {%0,%1,%2,%3};" \
        : "+f"((d)[0]), "+f"((d)[1]), "+f"((d)[2]), "+f"((d)[3]) \
        : "r"((a)[0]), "r"((a)[1]), "r"((a)[2]), "r"((a)[3]), \
          "r"((b)[0]), "r"((b)[1]))

__device__ __forceinline__ float gelu_tanh(float x) {
    float x3 = x * x * x;
    return 0.5f * x * (1.0f + tanhf(0.7978845608028654f * (x + 0.044715f * x3)));
}

__device__ __forceinline__ void split_bf16(float v, __nv_bfloat16& h, __nv_bfloat16& l) {
    h = __float2bfloat16(v);
    l = __float2bfloat16(v - __bfloat162float(h));
}

// 64B-row SMEM swizzle: chunk(16B) index ^= (row>>1)&3  (row = off>>6)
__device__ __forceinline__ uint32_t sw64(uint32_t off) {
    return off ^ (((off >> 7) & 3u) << 4);
}

// ---------------------------------------------------------------------------
// Conversion: x (fp32 row-major) -> hi/lo bf16 (row-major)
// ---------------------------------------------------------------------------
__global__ void convert_x_kernel(const float* __restrict__ x,
                                 __nv_bfloat16* __restrict__ xh,
                                 __nv_bfloat16* __restrict__ xl) {
    size_t i4 = (size_t)blockIdx.x * blockDim.x + threadIdx.x;
    const float4 v = ((const float4*)x)[i4];
    __nv_bfloat16 h0, l0, h1, l1, h2, l2, h3, l3;
    split_bf16(v.x, h0, l0); split_bf16(v.y, h1, l1);
    split_bf16(v.z, h2, l2); split_bf16(v.w, h3, l3);
    ((__nv_bfloat162*)xh)[i4 * 2 + 0] = __nv_bfloat162(h0, h1);
    ((__nv_bfloat162*)xh)[i4 * 2 + 1] = __nv_bfloat162(h2, h3);
    ((__nv_bfloat162*)xl)[i4 * 2 + 0] = __nv_bfloat162(l0, l1);
    ((__nv_bfloat162*)xl)[i4 * 2 + 1] = __nv_bfloat162(l2, l3);
}

// ---------------------------------------------------------------------------
// Conversion: W [R][C] fp32 -> out [C][R] bf16 hi/lo (transpose + split)
// ---------------------------------------------------------------------------
__global__ void transpose_convert_kernel(const float* __restrict__ W,
                                         __nv_bfloat16* __restrict__ Bh,
                                         __nv_bfloat16* __restrict__ Bl,
                                         int R, int C) {
    __shared__ float tile[32][33];
    int c0 = blockIdx.x * 32, r0 = blockIdx.y * 32;
    int tx = threadIdx.x, ty = threadIdx.y;
    #pragma unroll
    for (int i = 0; i < 32; i += 8)
        tile[ty + i][tx] = W[(size_t)(r0 + ty + i) * C + c0 + tx];
    __syncthreads();
    #pragma unroll
    for (int i = 0; i < 32; i += 8) {
        float v = tile[tx][ty + i];
        size_t o = (size_t)(c0 + ty + i) * R + r0 + tx;
        __nv_bfloat16 h, l;
        split_bf16(v, h, l);
        Bh[o] = h; Bl[o] = l;
    }
}

// ---------------------------------------------------------------------------
// Gating kernel (validated in R1)
// ---------------------------------------------------------------------------
__global__ void gate_kernel(const float* __restrict__ x,
                            const float* __restrict__ tc,
                            const float* __restrict__ gW,
                            const float* __restrict__ gb,
                            const float* __restrict__ tmW,
                            const float* __restrict__ tmb) {
    int b = blockIdx.x;
    int t = threadIdx.x;

    float logit[4] = {0.f, 0.f, 0.f, 0.f};
    float modv[8]  = {0.f, 0.f, 0.f, 0.f, 0.f, 0.f, 0.f, 0.f};
    const float* xb = x + (size_t)b * NL * ND;

    for (int d = t; d < ND; d += 256) {
        float hs = 0.f, ws = 0.f, ps = 0.f;
        for (int l = 0;   l < 128; l++) hs += xb[(size_t)l * ND + d];
        for (int l = 128; l < 256; l++) ws += xb[(size_t)l * ND + d];
        for (int l = 256; l < 384; l++) ps += xb[(size_t)l * ND + d];
        float full = (hs + ws + ps) * (1.0f / 384.0f);
        float hp   = (hs + ps) * (1.0f / 256.0f);
        float wp   = (ws + ps) * (1.0f / 256.0f);
        #pragma unroll
        for (int e = 0; e < 4; e++) {
            const float* w = gW + (size_t)e * 3 * ND;
            logit[e] += full * w[d] + hp * w[ND + d] + wp * w[2 * ND + d];
        }
        float v = tc[(size_t)b * ND + d];
        float s = v / (1.0f + expf(-v));
        #pragma unroll
        for (int j = 0; j < 8; j++) modv[j] += s * tmW[(size_t)j * ND + d];
    }

    __shared__ float red[12][256];
    #pragma unroll
    for (int v = 0; v < 4; v++) red[v][t] = logit[v];
    #pragma unroll
    for (int v = 0; v < 8; v++) red[4 + v][t] = modv[v];
    __syncthreads();
    for (int s = 128; s > 0; s >>= 1) {
        if (t < s) {
            #pragma unroll
            for (int v = 0; v < 12; v++) red[v][t] += red[v][t + s];
        }
        __syncthreads();
    }

    if (t == 0) {
        float lg[4];
        #pragma unroll
        for (int e = 0; e < 4; e++) {
            float sc = red[4 + e][0] + tmb[e];
            float sh = red[8 + e][0] + tmb[4 + e];
            lg[e] = (red[e][0] + gb[e]) * (1.0f + sc) + sh;
        }
        float mx = fmaxf(fmaxf(lg[0], lg[1]), fmaxf(lg[2], lg[3]));
        float ex[4], sum = 0.f;
        #pragma unroll
        for (int e = 0; e < 4; e++) { ex[e] = expf(lg[e] - mx); sum += ex[e]; }
        float sc4[4];
        #pragma unroll
        for (int e = 0; e < 4; e++) sc4[e] = ex[e] / sum;
        int i1 = 0;
        for (int e = 1; e < 4; e++) if (sc4[e] > sc4[i1]) i1 = e;
        int i2 = -1;
        for (int e = 0; e < 4; e++) {
            if (e == i1) continue;
            if (i2 < 0 || sc4[e] > sc4[i2]) i2 = e;
        }
        float denom = sc4[i1] + sc4[i2] + 1e-8f;
        #pragma unroll
        for (int e = 0; e < 4; e++) g_w_be[b * 4 + e] = 0.0f;
        g_w_be[b * 4 + i1] = sc4[i1] / denom;
        g_w_be[b * 4 + i2] = sc4[i2] / denom;
    }
}

// ---------------------------------------------------------------------------
// mma.sync bf16x3 GEMM: C[3072 x N] = A[M x K] @ B[N x K]^T
// CTA tile 128x64, BK=32, 3-stage cp.async pipeline, 8 warps (4m x 2n),
// warp tile 32x32 via m16n8k16. 3 MMA passes: AhBh + AhBl + AlBh.
//   mode 0: Chi/Clo = split(gelu(acc + bias))
//   mode 1: Cf = acc + bias
//   mode 2: Cf += w_be * (acc + bias)
// ---------------------------------------------------------------------------
#define BM 128
#define BN 64
#define BK 32
#define STAGES 3
#define A_HALF 8192                       // BM*BK*2
#define B_HALF 4096                       // BN*BK*2
#define STAGE_BYTES (2 * A_HALF + 2 * B_HALF)   // 24576
#define SMEM_GEMM (STAGES * STAGE_BYTES)        // 73728

__global__ __launch_bounds__(256, 2)
void mma_gemm_kernel(const __nv_bfloat16* __restrict__ Ahi,
                     const __nv_bfloat16* __restrict__ Alo,
                     const __nv_bfloat16* __restrict__ Bhi,
                     const __nv_bfloat16* __restrict__ Blo,
                     const float* __restrict__ bias,
                     float* __restrict__ Cf,
                     __nv_bfloat16* __restrict__ Chi,
                     __nv_bfloat16* __restrict__ Clo,
                     int K, int N, int e, int mode)
{
    const int mt = blockIdx.y;
    float wgt = 1.0f;
    if (e >= 0) {
        int b = mt / 3, seg = mt % 3;
        if ((e == 1 && seg == 1) || (e == 2 && seg == 0)) return;  // mask==0
        wgt = g_w_be[b * NE + e];
        if (wgt == 0.0f) return;                                    // not selected
    }

    extern __shared__ char smem[];
    const uint32_t sbase = smem_to_u32(smem);
    const int tid  = threadIdx.x;
    const int wid  = tid >> 5;
    const int lane = tid & 31;
    const int wm   = wid >> 1;   // 0..3
    const int wn   = wid & 1;    // 0..1
    const int m0 = mt * BM;
    const int n0 = blockIdx.x * BN;

    const int nc = K / BK;

    // ---- stage loader: Ahi|Alo (128x32) + Bhi|Blo (64x32), 16B cp.async
    auto load_stage = [&](int kt, int s) {
        const uint32_t sb = sbase + s * STAGE_BYTES;
        #pragma unroll
        for (int h = 0; h < 2; h++) {
            const __nv_bfloat16* src = (h ? Alo : Ahi) + (size_t)m0 * K + kt;
            #pragma unroll
            for (int i = 0; i < 2; i++) {
                int idx = tid + 256 * i;
                int row = idx >> 2, ch = idx & 3;
                uint32_t off = sw64((uint32_t)(row * 64 + ch * 16));
                cp_async16(sb + h * A_HALF + off, src + (size_t)row * K + ch * 8);
            }
        }
        #pragma unroll
        for (int h = 0; h < 2; h++) {
            const __nv_bfloat16* src = (h ? Blo : Bhi) + (size_t)n0 * K + kt;
            int row = tid >> 2, ch = tid & 3;
            uint32_t off = sw64((uint32_t)(row * 64 + ch * 16));
            cp_async16(sb + 2 * A_HALF + h * B_HALF + off,
                       src + (size_t)row * K + ch * 8);
        }
        CP_COMMIT();
    };

    float acc[2][4][4];
    #pragma unroll
    for (int f = 0; f < 2; f++)
        #pragma unroll
        for (int g = 0; g < 4; g++)
            #pragma unroll
            for (int k = 0; k < 4; k++) acc[f][g][k] = 0.0f;

    // ldmatrix address components (per-lane, stage-independent)
    const int q = lane >> 3;
    // A: q0: rows m0-7 k0 | q1: rows m8-15 k0 | q2: rows m0-7 k8 | q3: m8-15 k8
    const int a_row = wm * 32 + (q & 1) * 8 + (lane & 7);
    const int a_colb = (q >> 1) * 16;
    // B: q0: n0-7 k0 | q1: n0-7 k8 | q2: n8-15 k0 | q3: n8-15 k8
    const int b_row_base = wn * 32 + (q >> 1) * 8 + (lane & 7);
    const int b_colb = (q & 1) * 16;

    auto compute_stage = [&](int s) {
        const uint32_t sb = sbase + s * STAGE_BYTES;
        #pragma unroll
        for (int ks = 0; ks < 2; ks++) {
            uint32_t a_hi[2][4], a_lo[2][4];
            #pragma unroll
            for (int f = 0; f < 2; f++) {
                uint32_t off = sw64((uint32_t)((a_row + f * 16) * 64 + ks * 32 + a_colb));
                LDSM_X4(a_hi[f], sb + off);
                LDSM_X4(a_lo[f], sb + A_HALF + off);
            }
            uint32_t b_hi[4][2], b_lo[4][2];
            #pragma unroll
            for (int g2 = 0; g2 < 2; g2++) {
                uint32_t off = sw64((uint32_t)((b_row_base + g2 * 16) * 64 + ks * 32 + b_colb));
                uint32_t r[4];
                LDSM_X4(r, sb + 2 * A_HALF + off);
                b_hi[2 * g2][0] = r[0]; b_hi[2 * g2][1] = r[1];
                b_hi[2 * g2 + 1][0] = r[2]; b_hi[2 * g2 + 1][1] = r[3];
                LDSM_X4(r, sb + 2 * A_HALF + B_HALF + off);
                b_lo[2 * g2][0] = r[0]; b_lo[2 * g2][1] = r[1];
                b_lo[2 * g2 + 1][0] = r[2]; b_lo[2 * g2 + 1][1] = r[3];
            }
            #pragma unroll
            for (int f = 0; f < 2; f++)
                #pragma unroll
                for (int g = 0; g < 4; g++) {
                    MMA_BF16(acc[f][g], a_hi[f], b_hi[g]);
                    MMA_BF16(acc[f][g], a_hi[f], b_lo[g]);
                    MMA_BF16(acc[f][g], a_lo[f], b_hi[g]);
                }
        }
    };

    // ---- pipeline
    load_stage(0, 0);
    load_stage(BK, 1);
    for (int c = 0; c < nc; c++) {
        if (c + 1 < nc) { CP_WAIT(1); } else { CP_WAIT(0); }
        __syncthreads();
        if (c + 2 < nc) load_stage((c + 2) * BK, (c + 2) % 3);
        compute_stage(c % 3);
        __syncthreads();
    }

    // ---- epilogue
    const int gid = lane >> 2, tig = lane & 3;
    #pragma unroll
    for (int f = 0; f < 2; f++) {
        #pragma unroll
        for (int g = 0; g < 4; g++) {
            const int col = n0 + wn * 32 + g * 8 + 2 * tig;
            const float2 bv = *(const float2*)(bias + col);
            #pragma unroll
            for (int half = 0; half < 2; half++) {
                const int row = m0 + wm * 32 + f * 16 + gid + half * 8;
                float v0 = acc[f][g][2 * half]     + bv.x;
                float v1 = acc[f][g][2 * half + 1] + bv.y;
                if (mode == 0) {
                    v0 = gelu_tanh(v0);
                    v1 = gelu_tanh(v1);
                    __nv_bfloat16 h0, l0, h1, l1;
                    split_bf16(v0, h0, l0);
                    split_bf16(v1, h1, l1);
                    size_t o = ((size_t)row * N + col) >> 1;
                    ((__nv_bfloat162*)Chi)[o] = __nv_bfloat162(h0, h1);
                    ((__nv_bfloat162*)Clo)[o] = __nv_bfloat162(l0, l1);
                } else if (mode == 1) {
                    *(float2*)(Cf + (size_t)row * N + col) = make_float2(v0, v1);
                } else {
                    float2* p = (float2*)(Cf + (size_t)row * N + col);
                    float2 cur = *p;
                    cur.x += wgt * v0;
                    cur.y += wgt * v1;
                    *p = cur;
                }
            }
        }
    }
}

// ---------------------------------------------------------------------------
// kernel_launch
// ---------------------------------------------------------------------------
extern "C" void kernel_launch(void* const* d_in, const int* in_sizes, int n_in,
                              void* d_out, int out_size)
{
    const float* x    = (const float*)d_in[0];
    const float* tc   = (const float*)d_in[1];
    const float* gW   = (const float*)d_in[2];
    const float* gb   = (const float*)d_in[3];
    const float* tmW  = (const float*)d_in[4];
    const float* tmb  = (const float*)d_in[5];
    const float* eW1  = (const float*)d_in[6];
    const float* eb1  = (const float*)d_in[7];
    const float* eW2  = (const float*)d_in[8];
    const float* eb2  = (const float*)d_in[9];
    const float* sW1  = (const float*)d_in[10];
    const float* sb1  = (const float*)d_in[11];
    const float* sW2  = (const float*)d_in[12];
    const float* sb2  = (const float*)d_in[13];
    float* out = (float*)d_out;

    __nv_bfloat16 *xh, *xl, *hh, *hl, *wth, *wtl;
    cudaGetSymbolAddress((void**)&xh,  g_x_hi);
    cudaGetSymbolAddress((void**)&xl,  g_x_lo);
    cudaGetSymbolAddress((void**)&hh,  g_h_hi);
    cudaGetSymbolAddress((void**)&hl,  g_h_lo);
    cudaGetSymbolAddress((void**)&wth, g_wt_hi);
    cudaGetSymbolAddress((void**)&wtl, g_wt_lo);

    cudaFuncSetAttribute(mma_gemm_kernel,
                         cudaFuncAttributeMaxDynamicSharedMemorySize, SMEM_GEMM);

    // --- conversions
    convert_x_kernel<<<(MTOT * ND) / (256 * 4), 256>>>(x, xh, xl);

    dim3 tb(32, 8);
    transpose_convert_kernel<<<dim3(NH / 32, ND / 32), tb>>>(sW1, wth + OFF_SW1T, wtl + OFF_SW1T, ND, NH);
    transpose_convert_kernel<<<dim3(ND / 32, NH / 32), tb>>>(sW2, wth + OFF_SW2T, wtl + OFF_SW2T, NH, ND);
    for (int e = 0; e < NE; e++) {
        transpose_convert_kernel<<<dim3(NH / 32, ND / 32), tb>>>(
            eW1 + (size_t)e * ND * NH, wth + OFF_EW1T(e), wtl + OFF_EW1T(e), ND, NH);
        transpose_convert_kernel<<<dim3(ND / 32, NH / 32), tb>>>(
            eW2 + (size_t)e * NH * ND, wth + OFF_EW2T(e), wtl + OFF_EW2T(e), NH, ND);
    }

    // --- gating
    gate_kernel<<<NB, 256>>>(x, tc, gW, gb, tmW, tmb);

    dim3 g1(NH / BN, MTOT / BM);  // (64, 24) GEMM1 (N=4096)
    dim3 g2(ND / BN, MTOT / BM);  // (16, 24) GEMM2 (N=1024)

    // Shared path
    mma_gemm_kernel<<<g1, 256, SMEM_GEMM>>>(
        xh, xl, wth + OFF_SW1T, wtl + OFF_SW1T, sb1,
        nullptr, hh, hl, ND, NH, -1, 0);
    mma_gemm_kernel<<<g2, 256, SMEM_GEMM>>>(
        hh, hl, wth + OFF_SW2T, wtl + OFF_SW2T, sb2,
        out, nullptr, nullptr, NH, ND, -1, 1);

    // Expert paths (blocks self-skip via g_w_be + segment mask)
    for (int e = 0; e < NE; e++) {
        mma_gemm_kernel<<<g1, 256, SMEM_GEMM>>>(
            xh, xl, wth + OFF_EW1T(e), wtl + OFF_EW1T(e), eb1 + (size_t)e * NH,
            nullptr, hh, hl, ND, NH, e, 0);
        mma_gemm_kernel<<<g2, 256, SMEM_GEMM>>>(
            hh, hl, wth + OFF_EW2T(e), wtl + OFF_EW2T(e), eb2 + (size_t)e * ND,
            out, nullptr, nullptr, NH, ND, e, 2);
    }
}

// round 4
// speedup vs baseline: 5.9953x; 1.5391x over previous
#include <cuda_runtime.h>
#include <cuda_bf16.h>
#include <cstdint>
#include <math.h>

// Problem constants
#define NB 8
#define NL 384
#define ND 1024
#define NE 4
#define NH 4096
#define MTOT (NB * NL)   // 3072 tokens

// ---------------------------------------------------------------------------
// Device scratch (static; no runtime allocation)
// ---------------------------------------------------------------------------
__device__ float g_w_be[NB * NE];
__device__ float g_gpart[NB][12][ND];    // gate partial column sums

__device__ __align__(16) __nv_bfloat16 g_x_hi[(size_t)MTOT * ND];
__device__ __align__(16) __nv_bfloat16 g_x_lo[(size_t)MTOT * ND];

// 5 h slabs (shared + 4 experts), hi/lo
__device__ __align__(16) __nv_bfloat16 g_h_hi[(size_t)5 * MTOT * NH];
__device__ __align__(16) __nv_bfloat16 g_h_lo[(size_t)5 * MTOT * NH];

// GEMM2 partials: 10 slices (5 paths x 2 K-halves), fp32
__device__ __align__(16) float g_part2[(size_t)10 * MTOT * ND];

// Transposed weights arena: all B operands stored [N][K] K-major bf16 hi/lo.
#define WT_TOTAL (40u * 1024u * 1024u)
__device__ __align__(16) __nv_bfloat16 g_wt_hi[WT_TOTAL];
__device__ __align__(16) __nv_bfloat16 g_wt_lo[WT_TOTAL];

#define OFF_SW1T  ((size_t)0)
#define OFF_SW2T  ((size_t)4 * 1024 * 1024)
#define OFF_EW1T(e) ((size_t)8  * 1024 * 1024 + (size_t)(e) * 4 * 1024 * 1024)
#define OFF_EW2T(e) ((size_t)24 * 1024 * 1024 + (size_t)(e) * 4 * 1024 * 1024)

// ---------------------------------------------------------------------------
// Target-independent PTX helpers (sm_80+; compiles for plain sm_103)
// ---------------------------------------------------------------------------
__device__ __forceinline__ uint32_t smem_to_u32(const void* p) {
    uint32_t a;
    asm("{ .reg .u64 t; cvta.to.shared.u64 t, %1; cvt.u32.u64 %0, t; }"
        : "=r"(a) : "l"(p));
    return a;
}
__device__ __forceinline__ void cp_async16(uint32_t dst, const void* src) {
    asm volatile("cp.async.cg.shared.global [%0], [%1], 16;"
                 :: "r"(dst), "l"(src));
}
#define CP_COMMIT() asm volatile("cp.async.commit_group;" ::: "memory")
#define CP_WAIT(n)  asm volatile("cp.async.wait_group %0;" :: "n"(n) : "memory")

#define LDSM_X4(r, addr) \
    asm volatile("ldmatrix.sync.aligned.m8n8.x4.shared.b16 {%0,%1,%2,%3}, [%4];" \
        : "=r"((r)[0]), "=r"((r)[1]), "=r"((r)[2]), "=r"((r)[3]) \
        : "r"(addr))

#define MMA_BF16(d, a, b) \
    asm volatile("mma.sync.aligned.m16n8k16.row.col.f32.bf16.bf16.f32 " \
        "{%0,%1,%2,%3}, {%4,%5,%6,%7}, {%8,%9}, {%0,%1,%2,%3};" \
        : "+f"((d)[0]), "+f"((d)[1]), "+f"((d)[2]), "+f"((d)[3]) \
        : "r"((a)[0]), "r"((a)[1]), "r"((a)[2]), "r"((a)[3]), \
          "r"((b)[0]), "r"((b)[1]))

__device__ __forceinline__ float gelu_tanh(float x) {
    float x3 = x * x * x;
    return 0.5f * x * (1.0f + tanhf(0.7978845608028654f * (x + 0.044715f * x3)));
}
__device__ __forceinline__ void split_bf16(float v, __nv_bfloat16& h, __nv_bfloat16& l) {
    h = __float2bfloat16(v);
    l = __float2bfloat16(v - __bfloat162float(h));
}
// 64B-row SMEM swizzle
__device__ __forceinline__ uint32_t sw64(uint32_t off) {
    return off ^ (((off >> 7) & 3u) << 4);
}
// mask(e, seg): expert 1 skips seg 1 (wrist), expert 2 skips seg 0 (head)
__device__ __forceinline__ bool seg_masked(int e, int seg) {
    return (e == 1 && seg == 1) || (e == 2 && seg == 0);
}

// ---------------------------------------------------------------------------
// GEMM core: 128x128 CTA tile, BK=32, 3-stage cp.async, 8 warps (4m x 2n),
// warp tile 32x64, bf16x3 passes (AhBh + AhBl + AlBh), fp32 acc[2][8][4].
// ld = row stride (elements), Klen = summed length (multiple of 32).
// ---------------------------------------------------------------------------
#define BM 128
#define BN 128
#define BK 32
#define SUB_BYTES 8192                    // 128 rows x 64B
#define STAGE_BYTES (4 * SUB_BYTES)       // Ahi|Alo|Bhi|Blo = 32KB
#define SMEM_GEMM (3 * STAGE_BYTES)       // 96KB

__device__ __forceinline__ void gemm_mainloop(
    const __nv_bfloat16* __restrict__ Ahi, const __nv_bfloat16* __restrict__ Alo,
    const __nv_bfloat16* __restrict__ Bhi, const __nv_bfloat16* __restrict__ Blo,
    int ldA, int ldB, int Klen,
    uint32_t sbase, int tid, float acc[2][8][4])
{
    const int wid  = tid >> 5;
    const int lane = tid & 31;
    const int wm   = wid >> 1;   // 0..3
    const int wn   = wid & 1;    // 0..1
    const int nc = Klen / BK;

    // per-thread load coords: 2 chunks per sub-tile, 4 sub-tiles
    const int l_row = tid >> 2;          // 0..63 (idx = tid) ; +64 for second
    const int l_ch  = tid & 3;

    auto load_stage = [&](int kt, int s) {
        const uint32_t sb = sbase + s * STAGE_BYTES;
        const __nv_bfloat16* srcs[4] = {Ahi, Alo, Bhi, Blo};
        #pragma unroll
        for (int t = 0; t < 4; t++) {
            const int ld = (t < 2) ? ldA : ldB;
            const __nv_bfloat16* src = srcs[t] + kt;
            #pragma unroll
            for (int i = 0; i < 2; i++) {
                int row = l_row + 64 * i;
                uint32_t off = sw64((uint32_t)(row * 64 + l_ch * 16));
                cp_async16(sb + t * SUB_BYTES + off,
                           src + (size_t)row * ld + l_ch * 8);
            }
        }
        CP_COMMIT();
    };

    // ldmatrix coords
    const int q = lane >> 3;
    const int a_row  = wm * 32 + (q & 1) * 8 + (lane & 7);
    const int a_colb = (q >> 1) * 16;
    const int b_row  = wn * 64 + (q >> 1) * 8 + (lane & 7);
    const int b_colb = (q & 1) * 16;

    auto compute_stage = [&](int s) {
        const uint32_t sb = sbase + s * STAGE_BYTES;
        #pragma unroll
        for (int ks = 0; ks < 2; ks++) {
            uint32_t a_hi[2][4], a_lo[2][4];
            #pragma unroll
            for (int f = 0; f < 2; f++) {
                uint32_t off = sw64((uint32_t)((a_row + f * 16) * 64 + ks * 32 + a_colb));
                LDSM_X4(a_hi[f], sb + off);
                LDSM_X4(a_lo[f], sb + SUB_BYTES + off);
            }
            #pragma unroll
            for (int g2 = 0; g2 < 4; g2++) {
                uint32_t off = sw64((uint32_t)((b_row + g2 * 16) * 64 + ks * 32 + b_colb));
                uint32_t rh[4], rl[4];
                LDSM_X4(rh, sb + 2 * SUB_BYTES + off);
                LDSM_X4(rl, sb + 3 * SUB_BYTES + off);
                uint32_t bh0[2] = {rh[0], rh[1]}, bh1[2] = {rh[2], rh[3]};
                uint32_t bl0[2] = {rl[0], rl[1]}, bl1[2] = {rl[2], rl[3]};
                #pragma unroll
                for (int f = 0; f < 2; f++) {
                    MMA_BF16(acc[f][2 * g2],     a_hi[f], bh0);
                    MMA_BF16(acc[f][2 * g2],     a_hi[f], bl0);
                    MMA_BF16(acc[f][2 * g2],     a_lo[f], bh0);
                    MMA_BF16(acc[f][2 * g2 + 1], a_hi[f], bh1);
                    MMA_BF16(acc[f][2 * g2 + 1], a_hi[f], bl1);
                    MMA_BF16(acc[f][2 * g2 + 1], a_lo[f], bh1);
                }
            }
        }
    };

    load_stage(0, 0);
    load_stage(BK, 1);
    for (int c = 0; c < nc; c++) {
        if (c + 1 < nc) { CP_WAIT(1); } else { CP_WAIT(0); }
        __syncthreads();
        if (c + 2 < nc) load_stage((c + 2) * BK, (c + 2) % 3);
        compute_stage(c % 3);
        __syncthreads();
    }
}

// ---------------------------------------------------------------------------
// GEMM1 (merged): grid (NH/128=32, 24, 5). z=0 shared, z=e+1 expert.
// h[z] = gelu(x @ W1[z]^T + b1[z])  -> bf16 hi/lo slabs
// ---------------------------------------------------------------------------
__global__ __launch_bounds__(256, 2)
void gemm1_kernel(const __nv_bfloat16* __restrict__ xh,
                  const __nv_bfloat16* __restrict__ xl,
                  const __nv_bfloat16* __restrict__ wth,
                  const __nv_bfloat16* __restrict__ wtl,
                  const float* __restrict__ sb1,
                  const float* __restrict__ eb1)
{
    const int z = blockIdx.z;
    const int mt = blockIdx.y;
    if (z > 0) {
        int e = z - 1, b = mt / 3, seg = mt % 3;
        if (seg_masked(e, seg)) return;
        if (g_w_be[b * NE + e] == 0.0f) return;
    }
    extern __shared__ char smem[];
    const uint32_t sbase = smem_to_u32(smem);
    const int tid = threadIdx.x;
    const int m0 = mt * BM;
    const int n0 = blockIdx.x * BN;

    const size_t woff = (z == 0) ? OFF_SW1T : OFF_EW1T(z - 1);
    const float* bias = (z == 0) ? sb1 : eb1 + (size_t)(z - 1) * NH;

    float acc[2][8][4];
    #pragma unroll
    for (int f = 0; f < 2; f++)
        #pragma unroll
        for (int g = 0; g < 8; g++)
            #pragma unroll
            for (int k = 0; k < 4; k++) acc[f][g][k] = 0.0f;

    gemm_mainloop(xh + (size_t)m0 * ND, xl + (size_t)m0 * ND,
                  g_wt_hi + woff + (size_t)n0 * ND,
                  g_wt_lo + woff + (size_t)n0 * ND,
                  ND, ND, ND, sbase, tid, acc);

    // epilogue: gelu -> split -> bf16 hi/lo
    const int wid = tid >> 5, lane = tid & 31;
    const int wm = wid >> 1, wn = wid & 1;
    const int gid = lane >> 2, tig = lane & 3;
    __nv_bfloat16* Chi = g_h_hi + (size_t)z * MTOT * NH;
    __nv_bfloat16* Clo = g_h_lo + (size_t)z * MTOT * NH;
    #pragma unroll
    for (int f = 0; f < 2; f++) {
        #pragma unroll
        for (int g = 0; g < 8; g++) {
            const int col = n0 + wn * 64 + g * 8 + 2 * tig;
            const float2 bv = *(const float2*)(bias + col);
            #pragma unroll
            for (int half = 0; half < 2; half++) {
                const int row = m0 + wm * 32 + f * 16 + gid + half * 8;
                float v0 = gelu_tanh(acc[f][g][2 * half]     + bv.x);
                float v1 = gelu_tanh(acc[f][g][2 * half + 1] + bv.y);
                __nv_bfloat16 h0, l0, h1, l1;
                split_bf16(v0, h0, l0);
                split_bf16(v1, h1, l1);
                size_t o = ((size_t)row * NH + col) >> 1;
                ((__nv_bfloat162*)Chi)[o] = __nv_bfloat162(h0, h1);
                ((__nv_bfloat162*)Clo)[o] = __nv_bfloat162(l0, l1);
            }
        }
    }
}

// ---------------------------------------------------------------------------
// GEMM2 (merged + split-K): grid (ND/128=8, 24, 10). z -> (path p, khalf).
// part2[z] = h[p][.., kh*2048:+2048] @ W2[p][.., kh*2048:+2048]^T (+bias if kh==0)
// ---------------------------------------------------------------------------
__global__ __launch_bounds__(256, 2)
void gemm2_kernel(const float* __restrict__ sb2,
                  const float* __restrict__ eb2)
{
    const int z = blockIdx.z;
    const int p = z >> 1, kh = z & 1;
    const int mt = blockIdx.y;
    if (p > 0) {
        int e = p - 1, b = mt / 3, seg = mt % 3;
        if (seg_masked(e, seg)) return;
        if (g_w_be[b * NE + e] == 0.0f) return;
    }
    extern __shared__ char smem[];
    const uint32_t sbase = smem_to_u32(smem);
    const int tid = threadIdx.x;
    const int m0 = mt * BM;
    const int n0 = blockIdx.x * BN;
    const int k0 = kh * (NH / 2);

    const size_t woff = (p == 0) ? OFF_SW2T : OFF_EW2T(p - 1);
    const float* bias = (p == 0) ? sb2 : eb2 + (size_t)(p - 1) * ND;

    float acc[2][8][4];
    #pragma unroll
    for (int f = 0; f < 2; f++)
        #pragma unroll
        for (int g = 0; g < 8; g++)
            #pragma unroll
            for (int k = 0; k < 4; k++) acc[f][g][k] = 0.0f;

    gemm_mainloop(g_h_hi + (size_t)p * MTOT * NH + (size_t)m0 * NH + k0,
                  g_h_lo + (size_t)p * MTOT * NH + (size_t)m0 * NH + k0,
                  g_wt_hi + woff + (size_t)n0 * NH + k0,
                  g_wt_lo + woff + (size_t)n0 * NH + k0,
                  NH, NH, NH / 2, sbase, tid, acc);

    // epilogue: fp32 partial write (bias folded into kh==0 slice)
    const int wid = tid >> 5, lane = tid & 31;
    const int wm = wid >> 1, wn = wid & 1;
    const int gid = lane >> 2, tig = lane & 3;
    float* P = g_part2 + (size_t)z * MTOT * ND;
    #pragma unroll
    for (int f = 0; f < 2; f++) {
        #pragma unroll
        for (int g = 0; g < 8; g++) {
            const int col = n0 + wn * 64 + g * 8 + 2 * tig;
            float2 bv = make_float2(0.f, 0.f);
            if (kh == 0) bv = *(const float2*)(bias + col);
            #pragma unroll
            for (int half = 0; half < 2; half++) {
                const int row = m0 + wm * 32 + f * 16 + gid + half * 8;
                float v0 = acc[f][g][2 * half]     + bv.x;
                float v1 = acc[f][g][2 * half + 1] + bv.y;
                *(float2*)(P + (size_t)row * ND + col) = make_float2(v0, v1);
            }
        }
    }
}

// ---------------------------------------------------------------------------
// Final weighted reduction: out = part[shared] + sum_e w_be*mask*part[e]
// ---------------------------------------------------------------------------
__global__ void reduce_kernel(float* __restrict__ out) {
    size_t i4 = (size_t)blockIdx.x * blockDim.x + threadIdx.x;
    size_t i = i4 * 4;
    int row = (int)(i >> 10);       // / ND
    int b = row / NL, l = row % NL;
    int seg = l >> 7;

    const float4* P = (const float4*)g_part2;
    const size_t S = (size_t)MTOT * ND / 4;

    float4 a0 = P[i4], a1 = P[S + i4];
    float4 s = make_float4(a0.x + a1.x, a0.y + a1.y, a0.z + a1.z, a0.w + a1.w);
    #pragma unroll
    for (int e = 0; e < 4; e++) {
        if (seg_masked(e, seg)) continue;
        float w = g_w_be[b * NE + e];
        if (w == 0.0f) continue;
        float4 p0 = P[(size_t)(2 + 2 * e) * S + i4];
        float4 p1 = P[(size_t)(3 + 2 * e) * S + i4];
        s.x += w * (p0.x + p1.x);
        s.y += w * (p0.y + p1.y);
        s.z += w * (p0.z + p1.z);
        s.w += w * (p0.w + p1.w);
    }
    ((float4*)out)[i4] = s;
}

// ---------------------------------------------------------------------------
// Conversions
// ---------------------------------------------------------------------------
__global__ void convert_x_kernel(const float* __restrict__ x,
                                 __nv_bfloat16* __restrict__ xh,
                                 __nv_bfloat16* __restrict__ xl) {
    size_t i4 = (size_t)blockIdx.x * blockDim.x + threadIdx.x;
    const float4 v = ((const float4*)x)[i4];
    __nv_bfloat16 h0, l0, h1, l1, h2, l2, h3, l3;
    split_bf16(v.x, h0, l0); split_bf16(v.y, h1, l1);
    split_bf16(v.z, h2, l2); split_bf16(v.w, h3, l3);
    ((__nv_bfloat162*)xh)[i4 * 2 + 0] = __nv_bfloat162(h0, h1);
    ((__nv_bfloat162*)xh)[i4 * 2 + 1] = __nv_bfloat162(h2, h3);
    ((__nv_bfloat162*)xl)[i4 * 2 + 0] = __nv_bfloat162(l0, l1);
    ((__nv_bfloat162*)xl)[i4 * 2 + 1] = __nv_bfloat162(l2, l3);
}

// Batched transpose+split: 5 matrices [R][C] -> [C][R] hi/lo at dst offsets.
// grid (C/32, R/32, 5), block (32,8).
__global__ void transpose_batch_kernel(const float* __restrict__ src0,
                                       const float* __restrict__ srcE,
                                       size_t dstOff0, size_t dstOffE,
                                       size_t dstStrideE, int R, int C) {
    __shared__ float tile[32][33];
    int z = blockIdx.z;
    const float* W = (z == 0) ? src0 : srcE + (size_t)(z - 1) * R * C;
    size_t doff = (z == 0) ? dstOff0 : dstOffE + (size_t)(z - 1) * dstStrideE;
    int c0 = blockIdx.x * 32, r0 = blockIdx.y * 32;
    int tx = threadIdx.x, ty = threadIdx.y;
    #pragma unroll
    for (int i = 0; i < 32; i += 8)
        tile[ty + i][tx] = W[(size_t)(r0 + ty + i) * C + c0 + tx];
    __syncthreads();
    #pragma unroll
    for (int i = 0; i < 32; i += 8) {
        float v = tile[tx][ty + i];
        size_t o = doff + (size_t)(c0 + ty + i) * R + r0 + tx;
        __nv_bfloat16 h, l;
        split_bf16(v, h, l);
        g_wt_hi[o] = h; g_wt_lo[o] = l;
    }
}

// ---------------------------------------------------------------------------
// Gating: phase A (column partial sums) + phase B (logits/softmax/top-2)
// ---------------------------------------------------------------------------
__global__ void gate_sum_kernel(const float* __restrict__ x) {
    int b = blockIdx.x, c = blockIdx.y;   // c: 32-row chunk, 0..11
    const float* xb = x + ((size_t)b * NL + c * 32) * ND;
    for (int d = threadIdx.x; d < ND; d += 256) {
        float s = 0.f;
        #pragma unroll 8
        for (int l = 0; l < 32; l++) s += xb[(size_t)l * ND + d];
        g_gpart[b][c][d] = s;
    }
}

__global__ void gate_final_kernel(const float* __restrict__ tc,
                                  const float* __restrict__ gW,
                                  const float* __restrict__ gb,
                                  const float* __restrict__ tmW,
                                  const float* __restrict__ tmb) {
    int b = blockIdx.x;
    int t = threadIdx.x;

    float logit[4] = {0.f, 0.f, 0.f, 0.f};
    float modv[8]  = {0.f, 0.f, 0.f, 0.f, 0.f, 0.f, 0.f, 0.f};

    for (int d = t; d < ND; d += 256) {
        float hs = 0.f, ws = 0.f, ps = 0.f;
        #pragma unroll
        for (int c = 0; c < 4; c++)  hs += g_gpart[b][c][d];
        #pragma unroll
        for (int c = 4; c < 8; c++)  ws += g_gpart[b][c][d];
        #pragma unroll
        for (int c = 8; c < 12; c++) ps += g_gpart[b][c][d];
        float full = (hs + ws + ps) * (1.0f / 384.0f);
        float hp   = (hs + ps) * (1.0f / 256.0f);
        float wp   = (ws + ps) * (1.0f / 256.0f);
        #pragma unroll
        for (int e = 0; e < 4; e++) {
            const float* w = gW + (size_t)e * 3 * ND;
            logit[e] += full * w[d] + hp * w[ND + d] + wp * w[2 * ND + d];
        }
        float v = tc[(size_t)b * ND + d];
        float s = v / (1.0f + expf(-v));
        #pragma unroll
        for (int j = 0; j < 8; j++) modv[j] += s * tmW[(size_t)j * ND + d];
    }

    __shared__ float red[12][256];
    #pragma unroll
    for (int v = 0; v < 4; v++) red[v][t] = logit[v];
    #pragma unroll
    for (int v = 0; v < 8; v++) red[4 + v][t] = modv[v];
    __syncthreads();
    for (int s = 128; s > 0; s >>= 1) {
        if (t < s) {
            #pragma unroll
            for (int v = 0; v < 12; v++) red[v][t] += red[v][t + s];
        }
        __syncthreads();
    }

    if (t == 0) {
        float lg[4];
        #pragma unroll
        for (int e = 0; e < 4; e++) {
            float sc = red[4 + e][0] + tmb[e];
            float sh = red[8 + e][0] + tmb[4 + e];
            lg[e] = (red[e][0] + gb[e]) * (1.0f + sc) + sh;
        }
        float mx = fmaxf(fmaxf(lg[0], lg[1]), fmaxf(lg[2], lg[3]));
        float ex[4], sum = 0.f;
        #pragma unroll
        for (int e = 0; e < 4; e++) { ex[e] = expf(lg[e] - mx); sum += ex[e]; }
        float sc4[4];
        #pragma unroll
        for (int e = 0; e < 4; e++) sc4[e] = ex[e] / sum;
        int i1 = 0;
        for (int e = 1; e < 4; e++) if (sc4[e] > sc4[i1]) i1 = e;
        int i2 = -1;
        for (int e = 0; e < 4; e++) {
            if (e == i1) continue;
            if (i2 < 0 || sc4[e] > sc4[i2]) i2 = e;
        }
        float denom = sc4[i1] + sc4[i2] + 1e-8f;
        #pragma unroll
        for (int e = 0; e < 4; e++) g_w_be[b * 4 + e] = 0.0f;
        g_w_be[b * 4 + i1] = sc4[i1] / denom;
        g_w_be[b * 4 + i2] = sc4[i2] / denom;
    }
}

// ---------------------------------------------------------------------------
// kernel_launch — 8 launches; #6 is gemm1 (what ncu -s5 -c1 captures)
// ---------------------------------------------------------------------------
extern "C" void kernel_launch(void* const* d_in, const int* in_sizes, int n_in,
                              void* d_out, int out_size)
{
    const float* x    = (const float*)d_in[0];
    const float* tc   = (const float*)d_in[1];
    const float* gW   = (const float*)d_in[2];
    const float* gb   = (const float*)d_in[3];
    const float* tmW  = (const float*)d_in[4];
    const float* tmb  = (const float*)d_in[5];
    const float* eW1  = (const float*)d_in[6];
    const float* eb1  = (const float*)d_in[7];
    const float* eW2  = (const float*)d_in[8];
    const float* eb2  = (const float*)d_in[9];
    const float* sW1  = (const float*)d_in[10];
    const float* sb1  = (const float*)d_in[11];
    const float* sW2  = (const float*)d_in[12];
    const float* sb2  = (const float*)d_in[13];
    float* out = (float*)d_out;

    __nv_bfloat16 *xh, *xl;
    cudaGetSymbolAddress((void**)&xh, g_x_hi);
    cudaGetSymbolAddress((void**)&xl, g_x_lo);
    __nv_bfloat16 *wth, *wtl;
    cudaGetSymbolAddress((void**)&wth, g_wt_hi);
    cudaGetSymbolAddress((void**)&wtl, g_wt_lo);

    cudaFuncSetAttribute(gemm1_kernel,
        cudaFuncAttributeMaxDynamicSharedMemorySize, SMEM_GEMM);
    cudaFuncSetAttribute(gemm2_kernel,
        cudaFuncAttributeMaxDynamicSharedMemorySize, SMEM_GEMM);

    // 1. x -> hi/lo
    convert_x_kernel<<<(MTOT * ND) / (256 * 4), 256>>>(x, xh, xl);
    // 2-3. gate
    gate_sum_kernel<<<dim3(NB, 12), 256>>>(x);
    gate_final_kernel<<<NB, 256>>>(tc, gW, gb, tmW, tmb);
    // 4-5. weight transposes (W1 family: R=1024,C=4096; W2 family: R=4096,C=1024)
    transpose_batch_kernel<<<dim3(NH / 32, ND / 32, 5), dim3(32, 8)>>>(
        sW1, eW1, OFF_SW1T, OFF_EW1T(0), (size_t)4 * 1024 * 1024, ND, NH);
    transpose_batch_kernel<<<dim3(ND / 32, NH / 32, 5), dim3(32, 8)>>>(
        sW2, eW2, OFF_SW2T, OFF_EW2T(0), (size_t)4 * 1024 * 1024, NH, ND);
    // 6. all GEMM1s (shared + 4 experts, self-skipping)
    gemm1_kernel<<<dim3(NH / BN, MTOT / BM, 5), 256, SMEM_GEMM>>>(
        xh, xl, wth, wtl, sb1, eb1);
    // 7. all GEMM2s (5 paths x split-K 2)
    gemm2_kernel<<<dim3(ND / BN, MTOT / BM, 10), 256, SMEM_GEMM>>>(sb2, eb2);
    // 8. weighted reduce -> out
    reduce_kernel<<<(MTOT * ND) / (256 * 4), 256>>>(out);
}

// round 5
// speedup vs baseline: 6.1314x; 1.0227x over previous
#include <cuda_runtime.h>
#include <cuda_bf16.h>
#include <cstdint>
#include <math.h>

// Problem constants
#define NB 8
#define NL 384
#define ND 1024
#define NE 4
#define NH 4096
#define MTOT (NB * NL)   // 3072 tokens

// ---------------------------------------------------------------------------
// Device scratch (static; no runtime allocation)
// ---------------------------------------------------------------------------
__device__ float g_w_be[NB * NE];
__device__ float g_gpart[NB][12][ND];    // gate partial column sums

__device__ __align__(16) __nv_bfloat16 g_x_hi[(size_t)MTOT * ND];
__device__ __align__(16) __nv_bfloat16 g_x_lo[(size_t)MTOT * ND];

// 5 h slabs (shared + 4 experts), hi/lo
__device__ __align__(16) __nv_bfloat16 g_h_hi[(size_t)5 * MTOT * NH];
__device__ __align__(16) __nv_bfloat16 g_h_lo[(size_t)5 * MTOT * NH];

// GEMM2 partials: 10 slices (5 paths x 2 K-halves), fp32
__device__ __align__(16) float g_part2[(size_t)10 * MTOT * ND];

// Transposed weights arena: all B operands stored [N][K] K-major bf16 hi/lo.
#define WT_TOTAL (40u * 1024u * 1024u)
__device__ __align__(16) __nv_bfloat16 g_wt_hi[WT_TOTAL];
__device__ __align__(16) __nv_bfloat16 g_wt_lo[WT_TOTAL];

#define OFF_SW1T  ((size_t)0)
#define OFF_SW2T  ((size_t)4 * 1024 * 1024)
#define OFF_EW1T(e) ((size_t)8  * 1024 * 1024 + (size_t)(e) * 4 * 1024 * 1024)
#define OFF_EW2T(e) ((size_t)24 * 1024 * 1024 + (size_t)(e) * 4 * 1024 * 1024)

// ---------------------------------------------------------------------------
// Target-independent PTX helpers (sm_80+; compiles for plain sm_103)
// ---------------------------------------------------------------------------
__device__ __forceinline__ uint32_t smem_to_u32(const void* p) {
    uint32_t a;
    asm("{ .reg .u64 t; cvta.to.shared.u64 t, %1; cvt.u32.u64 %0, t; }"
        : "=r"(a) : "l"(p));
    return a;
}
__device__ __forceinline__ void cp_async16(uint32_t dst, const void* src) {
    asm volatile("cp.async.cg.shared.global [%0], [%1], 16;"
                 :: "r"(dst), "l"(src));
}
#define CP_COMMIT() asm volatile("cp.async.commit_group;" ::: "memory")
#define CP_WAIT(n)  asm volatile("cp.async.wait_group %0;" :: "n"(n) : "memory")

#define LDSM_X4(r, addr) \
    asm volatile("ldmatrix.sync.aligned.m8n8.x4.shared.b16 {%0,%1,%2,%3}, [%4];" \
        : "=r"((r)[0]), "=r"((r)[1]), "=r"((r)[2]), "=r"((r)[3]) \
        : "r"(addr))

#define MMA_BF16(d, a, b) \
    asm volatile("mma.sync.aligned.m16n8k16.row.col.f32.bf16.bf16.f32 " \
        "{%0,%1,%2,%3}, {%4,%5,%6,%7}, {%8,%9}, {%0,%1,%2,%3};" \
        : "+f"((d)[0]), "+f"((d)[1]), "+f"((d)[2]), "+f"((d)[3]) \
        : "r"((a)[0]), "r"((a)[1]), "r"((a)[2]), "r"((a)[3]), \
          "r"((b)[0]), "r"((b)[1]))

__device__ __forceinline__ float gelu_tanh(float x) {
    float x3 = x * x * x;
    return 0.5f * x * (1.0f + tanhf(0.7978845608028654f * (x + 0.044715f * x3)));
}
__device__ __forceinline__ void split_bf16(float v, __nv_bfloat16& h, __nv_bfloat16& l) {
    h = __float2bfloat16(v);
    l = __float2bfloat16(v - __bfloat162float(h));
}
// 64B-row SMEM swizzle
__device__ __forceinline__ uint32_t sw64(uint32_t off) {
    return off ^ (((off >> 7) & 3u) << 4);
}
// mask(e, seg): expert 1 skips seg 1 (wrist), expert 2 skips seg 0 (head)
__device__ __forceinline__ bool seg_masked(int e, int seg) {
    return (e == 1 && seg == 1) || (e == 2 && seg == 0);
}

// ---------------------------------------------------------------------------
// GEMM core: 128x128 CTA tile, BK=32, 3-stage cp.async, 8 warps (4m x 2n),
// warp tile 32x64, bf16x3 passes (AhBh + AhBl + AlBh), fp32 acc[2][8][4].
// Single __syncthreads per iteration (3-stage distance protects buffers).
// ---------------------------------------------------------------------------
#define BM 128
#define BN 128
#define BK 32
#define SUB_BYTES 8192                    // 128 rows x 64B
#define STAGE_BYTES (4 * SUB_BYTES)       // Ahi|Alo|Bhi|Blo = 32KB
#define SMEM_GEMM (3 * STAGE_BYTES)       // 96KB

__device__ __forceinline__ void gemm_mainloop(
    const __nv_bfloat16* __restrict__ Ahi, const __nv_bfloat16* __restrict__ Alo,
    const __nv_bfloat16* __restrict__ Bhi, const __nv_bfloat16* __restrict__ Blo,
    int ldA, int ldB, int Klen,
    uint32_t sbase, int tid, float acc[2][8][4])
{
    const int wid  = tid >> 5;
    const int lane = tid & 31;
    const int wm   = wid >> 1;   // 0..3
    const int wn   = wid & 1;    // 0..1
    const int nc = Klen / BK;

    const int l_row = tid >> 2;
    const int l_ch  = tid & 3;

    auto load_stage = [&](int kt, int s) {
        const uint32_t sb = sbase + s * STAGE_BYTES;
        const __nv_bfloat16* srcs[4] = {Ahi, Alo, Bhi, Blo};
        #pragma unroll
        for (int t = 0; t < 4; t++) {
            const int ld = (t < 2) ? ldA : ldB;
            const __nv_bfloat16* src = srcs[t] + kt;
            #pragma unroll
            for (int i = 0; i < 2; i++) {
                int row = l_row + 64 * i;
                uint32_t off = sw64((uint32_t)(row * 64 + l_ch * 16));
                cp_async16(sb + t * SUB_BYTES + off,
                           src + (size_t)row * ld + l_ch * 8);
            }
        }
        CP_COMMIT();
    };

    // ldmatrix coords
    const int q = lane >> 3;
    const int a_row  = wm * 32 + (q & 1) * 8 + (lane & 7);
    const int a_colb = (q >> 1) * 16;
    const int b_row  = wn * 64 + (q >> 1) * 8 + (lane & 7);
    const int b_colb = (q & 1) * 16;

    auto compute_stage = [&](int s) {
        const uint32_t sb = sbase + s * STAGE_BYTES;
        #pragma unroll
        for (int ks = 0; ks < 2; ks++) {
            uint32_t a_hi[2][4], a_lo[2][4];
            #pragma unroll
            for (int f = 0; f < 2; f++) {
                uint32_t off = sw64((uint32_t)((a_row + f * 16) * 64 + ks * 32 + a_colb));
                LDSM_X4(a_hi[f], sb + off);
                LDSM_X4(a_lo[f], sb + SUB_BYTES + off);
            }
            #pragma unroll
            for (int g2 = 0; g2 < 4; g2++) {
                uint32_t off = sw64((uint32_t)((b_row + g2 * 16) * 64 + ks * 32 + b_colb));
                uint32_t rh[4], rl[4];
                LDSM_X4(rh, sb + 2 * SUB_BYTES + off);
                LDSM_X4(rl, sb + 3 * SUB_BYTES + off);
                uint32_t bh0[2] = {rh[0], rh[1]}, bh1[2] = {rh[2], rh[3]};
                uint32_t bl0[2] = {rl[0], rl[1]}, bl1[2] = {rl[2], rl[3]};
                #pragma unroll
                for (int f = 0; f < 2; f++) {
                    MMA_BF16(acc[f][2 * g2],     a_hi[f], bh0);
                    MMA_BF16(acc[f][2 * g2],     a_hi[f], bl0);
                    MMA_BF16(acc[f][2 * g2],     a_lo[f], bh0);
                    MMA_BF16(acc[f][2 * g2 + 1], a_hi[f], bh1);
                    MMA_BF16(acc[f][2 * g2 + 1], a_hi[f], bl1);
                    MMA_BF16(acc[f][2 * g2 + 1], a_lo[f], bh1);
                }
            }
        }
    };

    load_stage(0, 0);
    load_stage(BK, 1);
    for (int c = 0; c < nc; c++) {
        if (c + 1 < nc) { CP_WAIT(1); } else { CP_WAIT(0); }
        __syncthreads();
        if (c + 2 < nc) load_stage((c + 2) * BK, (c + 2) % 3);
        compute_stage(c % 3);
        // no trailing sync: next iteration's sync (after CP_WAIT) protects
        // buffer (c+3)%3 == c%3 reuse, which only conflicts with compute(c).
    }
}

// ---------------------------------------------------------------------------
// GEMM1 (merged): grid (NH/128=32, 24, 5). z=0 shared, z=e+1 expert.
// ---------------------------------------------------------------------------
__global__ __launch_bounds__(256, 2)
void gemm1_kernel(const __nv_bfloat16* __restrict__ xh,
                  const __nv_bfloat16* __restrict__ xl,
                  const __nv_bfloat16* __restrict__ wth,
                  const __nv_bfloat16* __restrict__ wtl,
                  const float* __restrict__ sb1,
                  const float* __restrict__ eb1)
{
    const int z = blockIdx.z;
    const int mt = blockIdx.y;
    if (z > 0) {
        int e = z - 1, b = mt / 3, seg = mt % 3;
        if (seg_masked(e, seg)) return;
        if (g_w_be[b * NE + e] == 0.0f) return;
    }
    extern __shared__ char smem[];
    const uint32_t sbase = smem_to_u32(smem);
    const int tid = threadIdx.x;
    const int m0 = mt * BM;
    const int n0 = blockIdx.x * BN;

    const size_t woff = (z == 0) ? OFF_SW1T : OFF_EW1T(z - 1);
    const float* bias = (z == 0) ? sb1 : eb1 + (size_t)(z - 1) * NH;

    float acc[2][8][4];
    #pragma unroll
    for (int f = 0; f < 2; f++)
        #pragma unroll
        for (int g = 0; g < 8; g++)
            #pragma unroll
            for (int k = 0; k < 4; k++) acc[f][g][k] = 0.0f;

    gemm_mainloop(xh + (size_t)m0 * ND, xl + (size_t)m0 * ND,
                  g_wt_hi + woff + (size_t)n0 * ND,
                  g_wt_lo + woff + (size_t)n0 * ND,
                  ND, ND, ND, sbase, tid, acc);

    const int wid = tid >> 5, lane = tid & 31;
    const int wm = wid >> 1, wn = wid & 1;
    const int gid = lane >> 2, tig = lane & 3;
    __nv_bfloat16* Chi = g_h_hi + (size_t)z * MTOT * NH;
    __nv_bfloat16* Clo = g_h_lo + (size_t)z * MTOT * NH;
    #pragma unroll
    for (int f = 0; f < 2; f++) {
        #pragma unroll
        for (int g = 0; g < 8; g++) {
            const int col = n0 + wn * 64 + g * 8 + 2 * tig;
            const float2 bv = *(const float2*)(bias + col);
            #pragma unroll
            for (int half = 0; half < 2; half++) {
                const int row = m0 + wm * 32 + f * 16 + gid + half * 8;
                float v0 = gelu_tanh(acc[f][g][2 * half]     + bv.x);
                float v1 = gelu_tanh(acc[f][g][2 * half + 1] + bv.y);
                __nv_bfloat16 h0, l0, h1, l1;
                split_bf16(v0, h0, l0);
                split_bf16(v1, h1, l1);
                size_t o = ((size_t)row * NH + col) >> 1;
                ((__nv_bfloat162*)Chi)[o] = __nv_bfloat162(h0, h1);
                ((__nv_bfloat162*)Clo)[o] = __nv_bfloat162(l0, l1);
            }
        }
    }
}

// ---------------------------------------------------------------------------
// GEMM2 (merged + split-K): grid (8, 24, 10). z -> (path p, khalf). Pure
// partials (bias applied in reduce).
// ---------------------------------------------------------------------------
__global__ __launch_bounds__(256, 2)
void gemm2_kernel()
{
    const int z = blockIdx.z;
    const int p = z >> 1, kh = z & 1;
    const int mt = blockIdx.y;
    if (p > 0) {
        int e = p - 1, b = mt / 3, seg = mt % 3;
        if (seg_masked(e, seg)) return;
        if (g_w_be[b * NE + e] == 0.0f) return;
    }
    extern __shared__ char smem[];
    const uint32_t sbase = smem_to_u32(smem);
    const int tid = threadIdx.x;
    const int m0 = mt * BM;
    const int n0 = blockIdx.x * BN;
    const int k0 = kh * (NH / 2);

    const size_t woff = (p == 0) ? OFF_SW2T : OFF_EW2T(p - 1);

    float acc[2][8][4];
    #pragma unroll
    for (int f = 0; f < 2; f++)
        #pragma unroll
        for (int g = 0; g < 8; g++)
            #pragma unroll
            for (int k = 0; k < 4; k++) acc[f][g][k] = 0.0f;

    gemm_mainloop(g_h_hi + (size_t)p * MTOT * NH + (size_t)m0 * NH + k0,
                  g_h_lo + (size_t)p * MTOT * NH + (size_t)m0 * NH + k0,
                  g_wt_hi + woff + (size_t)n0 * NH + k0,
                  g_wt_lo + woff + (size_t)n0 * NH + k0,
                  NH, NH, NH / 2, sbase, tid, acc);

    const int wid = tid >> 5, lane = tid & 31;
    const int wm = wid >> 1, wn = wid & 1;
    const int gid = lane >> 2, tig = lane & 3;
    float* P = g_part2 + (size_t)z * MTOT * ND;
    #pragma unroll
    for (int f = 0; f < 2; f++) {
        #pragma unroll
        for (int g = 0; g < 8; g++) {
            const int col = n0 + wn * 64 + g * 8 + 2 * tig;
            #pragma unroll
            for (int half = 0; half < 2; half++) {
                const int row = m0 + wm * 32 + f * 16 + gid + half * 8;
                *(float2*)(P + (size_t)row * ND + col) =
                    make_float2(acc[f][g][2 * half], acc[f][g][2 * half + 1]);
            }
        }
    }
}

// ---------------------------------------------------------------------------
// Final weighted reduction (+ biases):
// out = (Psh0+Psh1+sb2) + sum_e w_be*mask*(Pe0+Pe1+eb2[e])
// ---------------------------------------------------------------------------
__global__ void reduce_kernel(float* __restrict__ out,
                              const float* __restrict__ sb2,
                              const float* __restrict__ eb2) {
    size_t i4 = (size_t)blockIdx.x * blockDim.x + threadIdx.x;
    size_t i = i4 * 4;
    int row = (int)(i >> 10);       // / ND
    int d   = (int)(i & 1023);
    int b = row / NL, l = row % NL;
    int seg = l >> 7;

    const float4* P = (const float4*)g_part2;
    const size_t S = (size_t)MTOT * ND / 4;

    float4 a0 = P[i4], a1 = P[S + i4];
    const float4 bs = *(const float4*)(sb2 + d);
    float4 s = make_float4(a0.x + a1.x + bs.x, a0.y + a1.y + bs.y,
                           a0.z + a1.z + bs.z, a0.w + a1.w + bs.w);
    #pragma unroll
    for (int e = 0; e < 4; e++) {
        if (seg_masked(e, seg)) continue;
        float w = g_w_be[b * NE + e];
        if (w == 0.0f) continue;
        float4 p0 = P[(size_t)(2 + 2 * e) * S + i4];
        float4 p1 = P[(size_t)(3 + 2 * e) * S + i4];
        const float4 be = *(const float4*)(eb2 + e * ND + d);
        s.x += w * (p0.x + p1.x + be.x);
        s.y += w * (p0.y + p1.y + be.y);
        s.z += w * (p0.z + p1.z + be.z);
        s.w += w * (p0.w + p1.w + be.w);
    }
    ((float4*)out)[i4] = s;
}

// ---------------------------------------------------------------------------
// Conversions
// ---------------------------------------------------------------------------
__global__ void convert_x_kernel(const float* __restrict__ x,
                                 __nv_bfloat16* __restrict__ xh,
                                 __nv_bfloat16* __restrict__ xl) {
    size_t i4 = (size_t)blockIdx.x * blockDim.x + threadIdx.x;
    const float4 v = ((const float4*)x)[i4];
    __nv_bfloat16 h0, l0, h1, l1, h2, l2, h3, l3;
    split_bf16(v.x, h0, l0); split_bf16(v.y, h1, l1);
    split_bf16(v.z, h2, l2); split_bf16(v.w, h3, l3);
    ((__nv_bfloat162*)xh)[i4 * 2 + 0] = __nv_bfloat162(h0, h1);
    ((__nv_bfloat162*)xh)[i4 * 2 + 1] = __nv_bfloat162(h2, h3);
    ((__nv_bfloat162*)xl)[i4 * 2 + 0] = __nv_bfloat162(l0, l1);
    ((__nv_bfloat162*)xl)[i4 * 2 + 1] = __nv_bfloat162(l2, l3);
}

// Batched transpose+split, 64x64 tiles, bfloat162 stores (128B/warp).
// grid (C/64, R/64, 5), block (32,8).
__global__ void transpose_batch_kernel(const float* __restrict__ src0,
                                       const float* __restrict__ srcE,
                                       size_t dstOff0, size_t dstOffE,
                                       size_t dstStrideE, int R, int C) {
    __shared__ float tile[64][65];
    int z = blockIdx.z;
    const float* W = (z == 0) ? src0 : srcE + (size_t)(z - 1) * R * C;
    size_t doff = (z == 0) ? dstOff0 : dstOffE + (size_t)(z - 1) * dstStrideE;
    int c0 = blockIdx.x * 64, r0 = blockIdx.y * 64;
    int tx = threadIdx.x, ty = threadIdx.y;
    #pragma unroll
    for (int i = 0; i < 8; i++) {
        int r = i * 8 + ty;
        const float2 v = *(const float2*)(W + (size_t)(r0 + r) * C + c0 + 2 * tx);
        tile[r][2 * tx] = v.x;
        tile[r][2 * tx + 1] = v.y;
    }
    __syncthreads();
    #pragma unroll
    for (int i = 0; i < 8; i++) {
        int c = i * 8 + ty;
        float v0 = tile[2 * tx][c];
        float v1 = tile[2 * tx + 1][c];
        __nv_bfloat16 h0, l0, h1, l1;
        split_bf16(v0, h0, l0);
        split_bf16(v1, h1, l1);
        size_t o = (doff + (size_t)(c0 + c) * R + r0 + 2 * tx) >> 1;
        ((__nv_bfloat162*)g_wt_hi)[o] = __nv_bfloat162(h0, h1);
        ((__nv_bfloat162*)g_wt_lo)[o] = __nv_bfloat162(l0, l1);
    }
}

// ---------------------------------------------------------------------------
// Gating: phase A (column partial sums) + phase B (logits/softmax/top-2)
// ---------------------------------------------------------------------------
__global__ void gate_sum_kernel(const float* __restrict__ x) {
    int b = blockIdx.x, c = blockIdx.y;
    const float* xb = x + ((size_t)b * NL + c * 32) * ND;
    for (int d = threadIdx.x; d < ND; d += 256) {
        float s = 0.f;
        #pragma unroll 8
        for (int l = 0; l < 32; l++) s += xb[(size_t)l * ND + d];
        g_gpart[b][c][d] = s;
    }
}

__global__ void gate_final_kernel(const float* __restrict__ tc,
                                  const float* __restrict__ gW,
                                  const float* __restrict__ gb,
                                  const float* __restrict__ tmW,
                                  const float* __restrict__ tmb) {
    int b = blockIdx.x;
    int t = threadIdx.x;

    float logit[4] = {0.f, 0.f, 0.f, 0.f};
    float modv[8]  = {0.f, 0.f, 0.f, 0.f, 0.f, 0.f, 0.f, 0.f};

    for (int d = t; d < ND; d += 256) {
        float hs = 0.f, ws = 0.f, ps = 0.f;
        #pragma unroll
        for (int c = 0; c < 4; c++)  hs += g_gpart[b][c][d];
        #pragma unroll
        for (int c = 4; c < 8; c++)  ws += g_gpart[b][c][d];
        #pragma unroll
        for (int c = 8; c < 12; c++) ps += g_gpart[b][c][d];
        float full = (hs + ws + ps) * (1.0f / 384.0f);
        float hp   = (hs + ps) * (1.0f / 256.0f);
        float wp   = (ws + ps) * (1.0f / 256.0f);
        #pragma unroll
        for (int e = 0; e < 4; e++) {
            const float* w = gW + (size_t)e * 3 * ND;
            logit[e] += full * w[d] + hp * w[ND + d] + wp * w[2 * ND + d];
        }
        float v = tc[(size_t)b * ND + d];
        float s = v / (1.0f + expf(-v));
        #pragma unroll
        for (int j = 0; j < 8; j++) modv[j] += s * tmW[(size_t)j * ND + d];
    }

    __shared__ float red[12][256];
    #pragma unroll
    for (int v = 0; v < 4; v++) red[v][t] = logit[v];
    #pragma unroll
    for (int v = 0; v < 8; v++) red[4 + v][t] = modv[v];
    __syncthreads();
    for (int s = 128; s > 0; s >>= 1) {
        if (t < s) {
            #pragma unroll
            for (int v = 0; v < 12; v++) red[v][t] += red[v][t + s];
        }
        __syncthreads();
    }

    if (t == 0) {
        float lg[4];
        #pragma unroll
        for (int e = 0; e < 4; e++) {
            float sc = red[4 + e][0] + tmb[e];
            float sh = red[8 + e][0] + tmb[4 + e];
            lg[e] = (red[e][0] + gb[e]) * (1.0f + sc) + sh;
        }
        float mx = fmaxf(fmaxf(lg[0], lg[1]), fmaxf(lg[2], lg[3]));
        float ex[4], sum = 0.f;
        #pragma unroll
        for (int e = 0; e < 4; e++) { ex[e] = expf(lg[e] - mx); sum += ex[e]; }
        float sc4[4];
        #pragma unroll
        for (int e = 0; e < 4; e++) sc4[e] = ex[e] / sum;
        int i1 = 0;
        for (int e = 1; e < 4; e++) if (sc4[e] > sc4[i1]) i1 = e;
        int i2 = -1;
        for (int e = 0; e < 4; e++) {
            if (e == i1) continue;
            if (i2 < 0 || sc4[e] > sc4[i2]) i2 = e;
        }
        float denom = sc4[i1] + sc4[i2] + 1e-8f;
        #pragma unroll
        for (int e = 0; e < 4; e++) g_w_be[b * 4 + e] = 0.0f;
        g_w_be[b * 4 + i1] = sc4[i1] / denom;
        g_w_be[b * 4 + i2] = sc4[i2] / denom;
    }
}

// ---------------------------------------------------------------------------
// kernel_launch — fork/join streams: gate | W1T | W2T run parallel to
// convert_x; W2T hides under gemm1.
// ---------------------------------------------------------------------------
extern "C" void kernel_launch(void* const* d_in, const int* in_sizes, int n_in,
                              void* d_out, int out_size)
{
    const float* x    = (const float*)d_in[0];
    const float* tc   = (const float*)d_in[1];
    const float* gW   = (const float*)d_in[2];
    const float* gb   = (const float*)d_in[3];
    const float* tmW  = (const float*)d_in[4];
    const float* tmb  = (const float*)d_in[5];
    const float* eW1  = (const float*)d_in[6];
    const float* eb1  = (const float*)d_in[7];
    const float* eW2  = (const float*)d_in[8];
    const float* eb2  = (const float*)d_in[9];
    const float* sW1  = (const float*)d_in[10];
    const float* sb1  = (const float*)d_in[11];
    const float* sW2  = (const float*)d_in[12];
    const float* sb2  = (const float*)d_in[13];
    float* out = (float*)d_out;

    __nv_bfloat16 *xh, *xl, *wth, *wtl;
    cudaGetSymbolAddress((void**)&xh, g_x_hi);
    cudaGetSymbolAddress((void**)&xl, g_x_lo);
    cudaGetSymbolAddress((void**)&wth, g_wt_hi);
    cudaGetSymbolAddress((void**)&wtl, g_wt_lo);

    static bool s_init = false;
    static cudaStream_t s1, s2, s3;
    static cudaEvent_t evRoot, ev1, ev2, ev3;
    if (!s_init) {
        cudaStreamCreateWithFlags(&s1, cudaStreamNonBlocking);
        cudaStreamCreateWithFlags(&s2, cudaStreamNonBlocking);
        cudaStreamCreateWithFlags(&s3, cudaStreamNonBlocking);
        cudaEventCreateWithFlags(&evRoot, cudaEventDisableTiming);
        cudaEventCreateWithFlags(&ev1, cudaEventDisableTiming);
        cudaEventCreateWithFlags(&ev2, cudaEventDisableTiming);
        cudaEventCreateWithFlags(&ev3, cudaEventDisableTiming);
        cudaFuncSetAttribute(gemm1_kernel,
            cudaFuncAttributeMaxDynamicSharedMemorySize, SMEM_GEMM);
        cudaFuncSetAttribute(gemm2_kernel,
            cudaFuncAttributeMaxDynamicSharedMemorySize, SMEM_GEMM);
        s_init = true;
    }

    // Fork
    cudaEventRecord(evRoot, 0);
    cudaStreamWaitEvent(s1, evRoot, 0);
    cudaStreamWaitEvent(s2, evRoot, 0);
    cudaStreamWaitEvent(s3, evRoot, 0);

    // main stream: x -> hi/lo
    convert_x_kernel<<<(MTOT * ND) / (256 * 4), 256>>>(x, xh, xl);
    // s1: gate chain
    gate_sum_kernel<<<dim3(NB, 12), 256, 0, s1>>>(x);
    gate_final_kernel<<<NB, 256, 0, s1>>>(tc, gW, gb, tmW, tmb);
    cudaEventRecord(ev1, s1);
    // s2: W1 transposes ([1024][4096] -> [4096][1024])
    transpose_batch_kernel<<<dim3(NH / 64, ND / 64, 5), dim3(32, 8), 0, s2>>>(
        sW1, eW1, OFF_SW1T, OFF_EW1T(0), (size_t)4 * 1024 * 1024, ND, NH);
    cudaEventRecord(ev2, s2);
    // s3: W2 transposes ([4096][1024] -> [1024][4096]) — hidden under gemm1
    transpose_batch_kernel<<<dim3(ND / 64, NH / 64, 5), dim3(32, 8), 0, s3>>>(
        sW2, eW2, OFF_SW2T, OFF_EW2T(0), (size_t)4 * 1024 * 1024, NH, ND);
    cudaEventRecord(ev3, s3);

    // join for gemm1: needs convert (in-stream), gate (ev1), W1T (ev2)
    cudaStreamWaitEvent(0, ev1, 0);
    cudaStreamWaitEvent(0, ev2, 0);
    gemm1_kernel<<<dim3(NH / BN, MTOT / BM, 5), 256, SMEM_GEMM>>>(
        xh, xl, wth, wtl, sb1, eb1);
    // join for gemm2: additionally W2T (ev3)
    cudaStreamWaitEvent(0, ev3, 0);
    gemm2_kernel<<<dim3(ND / BN, MTOT / BM, 10), 256, SMEM_GEMM>>>();
    reduce_kernel<<<(MTOT * ND) / (256 * 4), 256>>>(out, sb2, eb2);
}